// round 2
// baseline (speedup 1.0000x reference)
#include <cuda_runtime.h>
#include <math.h>

// ---------------------------------------------------------------------------
// FourSequenceMHAttention: B=8, H=8, S=2176 (64+1024+64+1024), DH=128
// k1: tiled QKV projection (W staged in smem) -> g_qkv[3][B][H][S][DH]
// k2: fp32 flash attention, packed f32x2 math  -> g_att[B][H][S][DH]
// k3: output projection (H*DH -> DH) + bias    -> out[B][S][DH]
// ---------------------------------------------------------------------------

namespace cfg {
constexpr int kB = 8, kH = 8, kNF = 64, kNU = 1024;
constexpr int kS = 2176, kDF = 64, kDU = 32, kDH = 128;
constexpr int QT = 32, KT = 64;                  // attention tile sizes
constexpr float kScale = 0.08838834764831845f;   // 1/sqrt(128)
}
using namespace cfg;

// Scratch (device globals: allocation-free per harness rules)
__device__ float g_qkv[3ull * kB * kH * kS * kDH];   // ~214 MB
__device__ float g_att[(size_t)kB * kH * kS * kDH];  // ~71 MB

// ---------------------------------------------------------------------------
// packed f32x2 helpers (sm_100+): two IEEE fp32 FMAs per instruction
// ---------------------------------------------------------------------------
typedef unsigned long long ull;
__device__ __forceinline__ ull pack2(float lo, float hi) {
    ull r; asm("mov.b64 %0, {%1,%2};" : "=l"(r) : "f"(lo), "f"(hi)); return r;
}
__device__ __forceinline__ void unpack2(ull v, float& lo, float& hi) {
    asm("mov.b64 {%0,%1}, %2;" : "=f"(lo), "=f"(hi) : "l"(v));
}
__device__ __forceinline__ ull fma2(ull a, ull b, ull c) {
    ull d; asm("fma.rn.f32x2 %0, %1, %2, %3;" : "=l"(d) : "l"(a), "l"(b), "l"(c)); return d;
}
__device__ __forceinline__ ull mul2(ull a, ull b) {
    ull d; asm("mul.rn.f32x2 %0, %1, %2;" : "=l"(d) : "l"(a), "l"(b)); return d;
}

__device__ __forceinline__ float warp_max(float v) {
#pragma unroll
    for (int o = 16; o; o >>= 1) v = fmaxf(v, __shfl_xor_sync(0xffffffffu, v, o));
    return v;
}
__device__ __forceinline__ float warp_sum(float v) {
#pragma unroll
    for (int o = 16; o; o >>= 1) v += __shfl_xor_sync(0xffffffffu, v, o);
    return v;
}

// ---------------------------------------------------------------------------
// Kernel 1: QKV projection as a tiled GEMM.
// Block: 256 threads, one (32-row s-tile, k, b, h). W[(h,p,k)] staged in smem
// (<=32KB) and reused across 32 rows -> W L2 traffic ~13056 * 32KB ~ 0.4GB.
// Thread (tw=t>>5, tc=t&31): rows {tw, tw+8, tw+16, tw+24}, cols tc*4..tc*4+3.
// ---------------------------------------------------------------------------
__global__ __launch_bounds__(256) void proj_kernel(
    const float* __restrict__ f0, const float* __restrict__ u0,
    const float* __restrict__ f1, const float* __restrict__ u1,
    const float* __restrict__ Wf, const float* __restrict__ bf,
    const float* __restrict__ Wu, const float* __restrict__ bu)
{
    __shared__ float sW[kDF * kDH];   // up to 64 x 128 = 32KB
    __shared__ float sx[32 * kDF];    // 32 rows x Din    = 8KB max

    const int tile = blockIdx.x;      // 0..67 (32-row s-tiles)
    const int k    = blockIdx.y;      // 0..2 (q/k/v)
    const int bh   = blockIdx.z;
    const int b = bh >> 3, h = bh & 7;

    const float* x; const float* W; const float* bias;
    int Din, p, s0, n0, rows;
    if (tile < 2)       { x=f0; W=Wf; bias=bf; Din=kDF; p=0; n0=tile*32;      s0=n0;              rows=kNF; }
    else if (tile < 34) { x=u0; W=Wu; bias=bu; Din=kDU; p=0; n0=(tile-2)*32;  s0=kNF+n0;          rows=kNU; }
    else if (tile < 36) { x=f1; W=Wf; bias=bf; Din=kDF; p=1; n0=(tile-34)*32; s0=kNF+kNU+n0;      rows=kNF; }
    else                { x=u1; W=Wu; bias=bu; Din=kDU; p=1; n0=(tile-36)*32; s0=2*kNF+kNU+n0;    rows=kNU; }

    const int t = threadIdx.x;

    // stage W[(h,p,k)] : Din*128 floats
    const float* Wg = W + (size_t)(((h * 2 + p) * 3 + k) * Din) * kDH;
    for (int i = t; i < Din * kDH / 4; i += 256)
        reinterpret_cast<float4*>(sW)[i] = reinterpret_cast<const float4*>(Wg)[i];
    // stage x rows n0..n0+31
    const float* xg = x + ((size_t)b * rows + n0) * Din;
    for (int i = t; i < 32 * Din / 4; i += 256)
        reinterpret_cast<float4*>(sx)[i] = reinterpret_cast<const float4*>(xg)[i];
    __syncthreads();

    const int tw = t >> 5;   // warp id: rows tw, tw+8, tw+16, tw+24
    const int tc = t & 31;   // col group: tc*4 .. tc*4+3

    float acc[4][4];
#pragma unroll
    for (int i = 0; i < 4; i++)
#pragma unroll
        for (int j = 0; j < 4; j++) acc[i][j] = 0.f;

#pragma unroll 4
    for (int f = 0; f < Din; f++) {
        float4 wv = *reinterpret_cast<const float4*>(sW + f * kDH + tc * 4);
        float x0 = sx[(tw     ) * Din + f];
        float x1 = sx[(tw +  8) * Din + f];
        float x2 = sx[(tw + 16) * Din + f];
        float x3 = sx[(tw + 24) * Din + f];
        acc[0][0] = fmaf(x0, wv.x, acc[0][0]); acc[0][1] = fmaf(x0, wv.y, acc[0][1]);
        acc[0][2] = fmaf(x0, wv.z, acc[0][2]); acc[0][3] = fmaf(x0, wv.w, acc[0][3]);
        acc[1][0] = fmaf(x1, wv.x, acc[1][0]); acc[1][1] = fmaf(x1, wv.y, acc[1][1]);
        acc[1][2] = fmaf(x1, wv.z, acc[1][2]); acc[1][3] = fmaf(x1, wv.w, acc[1][3]);
        acc[2][0] = fmaf(x2, wv.x, acc[2][0]); acc[2][1] = fmaf(x2, wv.y, acc[2][1]);
        acc[2][2] = fmaf(x2, wv.z, acc[2][2]); acc[2][3] = fmaf(x2, wv.w, acc[2][3]);
        acc[3][0] = fmaf(x3, wv.x, acc[3][0]); acc[3][1] = fmaf(x3, wv.y, acc[3][1]);
        acc[3][2] = fmaf(x3, wv.z, acc[3][2]); acc[3][3] = fmaf(x3, wv.w, acc[3][3]);
    }

    const float* bg = bias + ((h * 2 + p) * 3 + k) * kDH;
    float4 bv = *reinterpret_cast<const float4*>(bg + tc * 4);
    const size_t obase = (size_t)k * kB * kH * kS * kDH
                       + ((size_t)b * kH + h) * kS * kDH + (size_t)s0 * kDH;
#pragma unroll
    for (int r = 0; r < 4; r++) {
        int row = tw + r * 8;
        float4 o = make_float4(acc[r][0] + bv.x, acc[r][1] + bv.y,
                               acc[r][2] + bv.z, acc[r][3] + bv.w);
        *reinterpret_cast<float4*>(&g_qkv[obase + (size_t)row * kDH + tc * 4]) = o;
    }
}

// ---------------------------------------------------------------------------
// Kernel 2: flash attention, fp32 with packed f32x2 math.
// Block = 256 threads (8 warps). Q tile 32 rows, K/V tile 64 rows.
// Warp w owns q-rows {w, w+8, w+16, w+24}. Lane owns k-cols {lane, lane+32}
// in QK^T and acc cols lane*4..+3 in PV (packed as pairs along DH).
// K stored as padded float2 ktp[dp][col] (dp = d/2): per-dp kv loads are
// LDS.64 [base + imm], conflict-free. Dynamic smem = 82,432 B.
// ---------------------------------------------------------------------------
constexpr int KTP_LD  = KT + 1;                       // 65 float2 per dp-row
constexpr int ATTN_SMEM_FLOATS = QT * kDH + 64 * KTP_LD * 2 + KT * kDH;
constexpr int ATTN_SMEM_BYTES  = ATTN_SMEM_FLOATS * 4;  // 82,432

__global__ __launch_bounds__(256, 2) void attn_kernel()
{
    extern __shared__ float smem[];
    float*  sQ  = smem;                              // 4096 floats
    float2* ktp = reinterpret_cast<float2*>(smem + QT * kDH);  // [64][65]
    float*  sV  = smem + QT * kDH + 64 * KTP_LD * 2; // 8192 floats

    const int t = threadIdx.x, w = t >> 5, lane = t & 31;
    const int qt = blockIdx.x, h = blockIdx.y, b = blockIdx.z;

    const size_t plane = (size_t)kS * kDH;
    const size_t base  = ((size_t)b * kH + h) * plane;
    const float* Qp = g_qkv + base + (size_t)qt * QT * kDH;
    const float* Kp = g_qkv + (size_t)kB * kH * plane + base;
    const float* Vp = g_qkv + 2ull * kB * kH * plane + base;

    // load Q tile (pre-scaled)
    for (int i = t; i < QT * kDH / 4; i += 256) {
        float4 q = reinterpret_cast<const float4*>(Qp)[i];
        q.x *= kScale; q.y *= kScale; q.z *= kScale; q.w *= kScale;
        reinterpret_cast<float4*>(sQ)[i] = q;
    }

    ull a[8];
#pragma unroll
    for (int i = 0; i < 8; i++) a[i] = 0ull;   // (0.0f, 0.0f)
    float m0 = -INFINITY, m1 = -INFINITY, m2 = -INFINITY, m3 = -INFINITY;
    float l0 = 0.f, l1 = 0.f, l2 = 0.f, l3 = 0.f;

    const ull* q0p = reinterpret_cast<const ull*>(sQ + (w     ) * kDH);
    const ull* q1p = reinterpret_cast<const ull*>(sQ + (w +  8) * kDH);
    const ull* q2p = reinterpret_cast<const ull*>(sQ + (w + 16) * kDH);
    const ull* q3p = reinterpret_cast<const ull*>(sQ + (w + 24) * kDH);
    const ull* kbA = reinterpret_cast<const ull*>(ktp) + lane;
    const ull* kbB = reinterpret_cast<const ull*>(ktp) + 32 + lane;

    for (int k0 = 0; k0 < kS; k0 += KT) {
        __syncthreads();  // prior-iteration reads of ktp/sV done (covers sQ on iter 0)

        // stage K tile: 64 rows x 64 float2, transposed-by-pairs into ktp[dp][col]
        {
            const float2* Kg = reinterpret_cast<const float2*>(Kp + (size_t)k0 * kDH);
#pragma unroll
            for (int j = 0; j < 16; j++) {
                int i = t + j * 256;          // 0..4095
                int col = i >> 6, dp = i & 63;
                reinterpret_cast<float2*>(ktp)[dp * KTP_LD + col] = Kg[i];
            }
        }
        // stage V tile: 64 x 128 natural
        {
            const float4* Vg = reinterpret_cast<const float4*>(Vp + (size_t)k0 * kDH);
#pragma unroll
            for (int j = 0; j < 8; j++)
                reinterpret_cast<float4*>(sV)[t + j * 256] = Vg[t + j * 256];
        }
        __syncthreads();

        // ---- S = Q K^T, packed pairs over d ----
        ull sa0 = 0, sa1 = 0, sa2 = 0, sa3 = 0;
        ull sb0 = 0, sb1 = 0, sb2 = 0, sb3 = 0;
#pragma unroll 16
        for (int dp = 0; dp < 64; dp++) {
            ull kva = kbA[dp * KTP_LD];
            ull kvb = kbB[dp * KTP_LD];
            ull qq0 = q0p[dp], qq1 = q1p[dp], qq2 = q2p[dp], qq3 = q3p[dp];
            sa0 = fma2(qq0, kva, sa0); sb0 = fma2(qq0, kvb, sb0);
            sa1 = fma2(qq1, kva, sa1); sb1 = fma2(qq1, kvb, sb1);
            sa2 = fma2(qq2, kva, sa2); sb2 = fma2(qq2, kvb, sb2);
            sa3 = fma2(qq3, kva, sa3); sb3 = fma2(qq3, kvb, sb3);
        }
        float lo, hi;
        float sa0f, sa1f, sa2f, sa3f, sb0f, sb1f, sb2f, sb3f;
        unpack2(sa0, lo, hi); sa0f = lo + hi;  unpack2(sb0, lo, hi); sb0f = lo + hi;
        unpack2(sa1, lo, hi); sa1f = lo + hi;  unpack2(sb1, lo, hi); sb1f = lo + hi;
        unpack2(sa2, lo, hi); sa2f = lo + hi;  unpack2(sb2, lo, hi); sb2f = lo + hi;
        unpack2(sa3, lo, hi); sa3f = lo + hi;  unpack2(sb3, lo, hi); sb3f = lo + hi;

        // ---- online softmax (warp-local: this warp owns these 4 rows) ----
        float n0 = fmaxf(m0, warp_max(fmaxf(sa0f, sb0f)));
        float n1 = fmaxf(m1, warp_max(fmaxf(sa1f, sb1f)));
        float n2 = fmaxf(m2, warp_max(fmaxf(sa2f, sb2f)));
        float n3 = fmaxf(m3, warp_max(fmaxf(sa3f, sb3f)));
        float c0 = __expf(m0 - n0), c1 = __expf(m1 - n1);
        float c2 = __expf(m2 - n2), c3 = __expf(m3 - n3);
        float pa0 = __expf(sa0f - n0), pb0 = __expf(sb0f - n0);
        float pa1 = __expf(sa1f - n1), pb1 = __expf(sb1f - n1);
        float pa2 = __expf(sa2f - n2), pb2 = __expf(sb2f - n2);
        float pa3 = __expf(sa3f - n3), pb3 = __expf(sb3f - n3);
        l0 = l0 * c0 + warp_sum(pa0 + pb0); m0 = n0;
        l1 = l1 * c1 + warp_sum(pa1 + pb1); m1 = n1;
        l2 = l2 * c2 + warp_sum(pa2 + pb2); m2 = n2;
        l3 = l3 * c3 + warp_sum(pa3 + pb3); m3 = n3;
        {
            ull cc0 = pack2(c0, c0), cc1 = pack2(c1, c1);
            ull cc2 = pack2(c2, c2), cc3 = pack2(c3, c3);
            a[0] = mul2(a[0], cc0); a[1] = mul2(a[1], cc0);
            a[2] = mul2(a[2], cc1); a[3] = mul2(a[3], cc1);
            a[4] = mul2(a[4], cc2); a[5] = mul2(a[5], cc2);
            a[6] = mul2(a[6], cc3); a[7] = mul2(a[7], cc3);
        }

        // ---- acc += P @ V : half 0 (keys k0..k0+31, P from pa*), half 1 (pb*) ----
#pragma unroll 8
        for (int kk = 0; kk < 32; kk++) {
            float4 vv = *reinterpret_cast<const float4*>(sV + kk * kDH + lane * 4);
            ull v01 = pack2(vv.x, vv.y), v23 = pack2(vv.z, vv.w);
            float b0 = __shfl_sync(0xffffffffu, pa0, kk);
            float b1 = __shfl_sync(0xffffffffu, pa1, kk);
            float b2 = __shfl_sync(0xffffffffu, pa2, kk);
            float b3 = __shfl_sync(0xffffffffu, pa3, kk);
            ull bb0 = pack2(b0, b0), bb1 = pack2(b1, b1);
            ull bb2 = pack2(b2, b2), bb3 = pack2(b3, b3);
            a[0] = fma2(bb0, v01, a[0]); a[1] = fma2(bb0, v23, a[1]);
            a[2] = fma2(bb1, v01, a[2]); a[3] = fma2(bb1, v23, a[3]);
            a[4] = fma2(bb2, v01, a[4]); a[5] = fma2(bb2, v23, a[5]);
            a[6] = fma2(bb3, v01, a[6]); a[7] = fma2(bb3, v23, a[7]);
        }
#pragma unroll 8
        for (int kk = 0; kk < 32; kk++) {
            float4 vv = *reinterpret_cast<const float4*>(sV + (32 + kk) * kDH + lane * 4);
            ull v01 = pack2(vv.x, vv.y), v23 = pack2(vv.z, vv.w);
            float b0 = __shfl_sync(0xffffffffu, pb0, kk);
            float b1 = __shfl_sync(0xffffffffu, pb1, kk);
            float b2 = __shfl_sync(0xffffffffu, pb2, kk);
            float b3 = __shfl_sync(0xffffffffu, pb3, kk);
            ull bb0 = pack2(b0, b0), bb1 = pack2(b1, b1);
            ull bb2 = pack2(b2, b2), bb3 = pack2(b3, b3);
            a[0] = fma2(bb0, v01, a[0]); a[1] = fma2(bb0, v23, a[1]);
            a[2] = fma2(bb1, v01, a[2]); a[3] = fma2(bb1, v23, a[3]);
            a[4] = fma2(bb2, v01, a[4]); a[5] = fma2(bb2, v23, a[5]);
            a[6] = fma2(bb3, v01, a[6]); a[7] = fma2(bb3, v23, a[7]);
        }
    }

    // ---- normalize + write O ----
    const float i0 = 1.f / l0, i1 = 1.f / l1, i2 = 1.f / l2, i3 = 1.f / l3;
    float* O = g_att + base + (size_t)qt * QT * kDH;
    float o0, o1, o2, o3;
    unpack2(a[0], o0, o1); unpack2(a[1], o2, o3);
    *reinterpret_cast<float4*>(O + (w     ) * kDH + lane * 4) = make_float4(o0*i0, o1*i0, o2*i0, o3*i0);
    unpack2(a[2], o0, o1); unpack2(a[3], o2, o3);
    *reinterpret_cast<float4*>(O + (w +  8) * kDH + lane * 4) = make_float4(o0*i1, o1*i1, o2*i1, o3*i1);
    unpack2(a[4], o0, o1); unpack2(a[5], o2, o3);
    *reinterpret_cast<float4*>(O + (w + 16) * kDH + lane * 4) = make_float4(o0*i2, o1*i2, o2*i2, o3*i2);
    unpack2(a[6], o0, o1); unpack2(a[7], o2, o3);
    *reinterpret_cast<float4*>(O + (w + 24) * kDH + lane * 4) = make_float4(o0*i3, o1*i3, o2*i3, o3*i3);
}

// ---------------------------------------------------------------------------
// Kernel 3: out[b,s,:] = concat_h(O[b,h,s,:]) @ Wout + bout
// ---------------------------------------------------------------------------
__global__ __launch_bounds__(256) void out_kernel(
    const float* __restrict__ Wout, const float* __restrict__ bout,
    float* __restrict__ out)
{
    __shared__ float ws[64 * kDH];  // 32 KB
    __shared__ float xs[16 * 64];   // 4 KB

    const int t = threadIdx.x;
    const int row = t >> 4;      // 0..15 : (b,s) row within block
    const int dj  = t & 15;      // output col base; cols d = dj + 16*j
    const int bs0 = blockIdx.x * 16;

    float acc[8];
#pragma unroll
    for (int j = 0; j < 8; j++) acc[j] = 0.f;

    for (int c = 0; c < 16; c++) {   // 16 chunks of 64 input features
        const int i0 = c * 64;
        __syncthreads();
        {
            const float4* Wsrc = reinterpret_cast<const float4*>(Wout + (size_t)i0 * kDH);
#pragma unroll
            for (int j = 0; j < 8; j++)
                reinterpret_cast<float4*>(ws)[t + j * 256] = Wsrc[t + j * 256];
        }
#pragma unroll
        for (int j = 0; j < 4; j++) {
            int i  = t + j * 256;          // 0..1023
            int r  = i >> 6, ii = i & 63;
            int gi = i0 + ii;
            int hh = gi >> 7, e = gi & 127;
            int bs = bs0 + r;
            int b  = bs / kS, s = bs % kS;
            xs[r * 64 + ii] = g_att[(((size_t)b * kH + hh) * kS + s) * kDH + e];
        }
        __syncthreads();

#pragma unroll 8
        for (int ii = 0; ii < 64; ii++) {
            float xv = xs[row * 64 + ii];
#pragma unroll
            for (int j = 0; j < 8; j++)
                acc[j] = fmaf(xv, ws[ii * kDH + dj + 16 * j], acc[j]);
        }
    }

    const int bs = bs0 + row;
#pragma unroll
    for (int j = 0; j < 8; j++) {
        int d = dj + 16 * j;
        out[(size_t)bs * kDH + d] = acc[j] + bout[d];
    }
}

// ---------------------------------------------------------------------------
extern "C" void kernel_launch(void* const* d_in, const int* in_sizes, int n_in,
                              void* d_out, int out_size)
{
    (void)in_sizes; (void)n_in; (void)out_size;
    const float* f0   = (const float*)d_in[0];
    const float* u0   = (const float*)d_in[1];
    const float* f1   = (const float*)d_in[2];
    const float* u1   = (const float*)d_in[3];
    const float* Wf   = (const float*)d_in[4];
    const float* bf   = (const float*)d_in[5];
    const float* Wu   = (const float*)d_in[6];
    const float* bu   = (const float*)d_in[7];
    const float* Wout = (const float*)d_in[8];
    const float* bout = (const float*)d_in[9];
    float* out = (float*)d_out;

    // idempotent; not a stream op, safe under graph capture
    cudaFuncSetAttribute(attn_kernel,
                         cudaFuncAttributeMaxDynamicSharedMemorySize, ATTN_SMEM_BYTES);

    proj_kernel<<<dim3(68, 3, kB * kH), 256>>>(f0, u0, f1, u1, Wf, bf, Wu, bu);
    attn_kernel<<<dim3(kS / QT, kH, kB), 256, ATTN_SMEM_BYTES>>>();
    out_kernel<<<(kB * kS) / 16, 256>>>(Wout, bout, out);
}

// round 4
// speedup vs baseline: 3.1178x; 3.1178x over previous
#include <cuda_runtime.h>
#include <math.h>

// ---------------------------------------------------------------------------
// FourSequenceMHAttention: B=8, H=8, S=2176 (64+1024+64+1024), DH=128
// k1: tiled QKV projection (W staged in smem) -> g_qkv[3][B][H][S][DH]
// k2: tf32 mma.sync flash attention            -> g_att[B][H][S][DH]
// k3: output projection (H*DH -> DH) + bias    -> out[B][S][DH]
// ---------------------------------------------------------------------------

namespace cfg {
constexpr int kB = 8, kH = 8, kNF = 64, kNU = 1024;
constexpr int kS = 2176, kDF = 64, kDU = 32, kDH = 128;
constexpr float kScale = 0.08838834764831845f;   // 1/sqrt(128)
}
using namespace cfg;

// Scratch (device globals: allocation-free per harness rules)
__device__ float g_qkv[3ull * kB * kH * kS * kDH];   // ~214 MB
__device__ float g_att[(size_t)kB * kH * kS * kDH];  // ~71 MB

// ---------------------------------------------------------------------------
// Kernel 1: QKV projection as a tiled GEMM (R2-measured: 112us, passing)
// ---------------------------------------------------------------------------
__global__ __launch_bounds__(256) void proj_kernel(
    const float* __restrict__ f0, const float* __restrict__ u0,
    const float* __restrict__ f1, const float* __restrict__ u1,
    const float* __restrict__ Wf, const float* __restrict__ bf,
    const float* __restrict__ Wu, const float* __restrict__ bu)
{
    __shared__ float sW[kDF * kDH];   // up to 64 x 128 = 32KB
    __shared__ float sx[32 * kDF];    // 32 rows x Din    = 8KB max

    const int tile = blockIdx.x;      // 0..67 (32-row s-tiles)
    const int k    = blockIdx.y;      // 0..2 (q/k/v)
    const int bh   = blockIdx.z;
    const int b = bh >> 3, h = bh & 7;

    const float* x; const float* W; const float* bias;
    int Din, p, s0, n0, rows;
    if (tile < 2)       { x=f0; W=Wf; bias=bf; Din=kDF; p=0; n0=tile*32;      s0=n0;              rows=kNF; }
    else if (tile < 34) { x=u0; W=Wu; bias=bu; Din=kDU; p=0; n0=(tile-2)*32;  s0=kNF+n0;          rows=kNU; }
    else if (tile < 36) { x=f1; W=Wf; bias=bf; Din=kDF; p=1; n0=(tile-34)*32; s0=kNF+kNU+n0;      rows=kNF; }
    else                { x=u1; W=Wu; bias=bu; Din=kDU; p=1; n0=(tile-36)*32; s0=2*kNF+kNU+n0;    rows=kNU; }

    const int t = threadIdx.x;

    const float* Wg = W + (size_t)(((h * 2 + p) * 3 + k) * Din) * kDH;
    for (int i = t; i < Din * kDH / 4; i += 256)
        reinterpret_cast<float4*>(sW)[i] = reinterpret_cast<const float4*>(Wg)[i];
    const float* xg = x + ((size_t)b * rows + n0) * Din;
    for (int i = t; i < 32 * Din / 4; i += 256)
        reinterpret_cast<float4*>(sx)[i] = reinterpret_cast<const float4*>(xg)[i];
    __syncthreads();

    const int tw = t >> 5;
    const int tc = t & 31;

    float acc[4][4];
#pragma unroll
    for (int i = 0; i < 4; i++)
#pragma unroll
        for (int j = 0; j < 4; j++) acc[i][j] = 0.f;

#pragma unroll 4
    for (int f = 0; f < Din; f++) {
        float4 wv = *reinterpret_cast<const float4*>(sW + f * kDH + tc * 4);
        float x0 = sx[(tw     ) * Din + f];
        float x1 = sx[(tw +  8) * Din + f];
        float x2 = sx[(tw + 16) * Din + f];
        float x3 = sx[(tw + 24) * Din + f];
        acc[0][0] = fmaf(x0, wv.x, acc[0][0]); acc[0][1] = fmaf(x0, wv.y, acc[0][1]);
        acc[0][2] = fmaf(x0, wv.z, acc[0][2]); acc[0][3] = fmaf(x0, wv.w, acc[0][3]);
        acc[1][0] = fmaf(x1, wv.x, acc[1][0]); acc[1][1] = fmaf(x1, wv.y, acc[1][1]);
        acc[1][2] = fmaf(x1, wv.z, acc[1][2]); acc[1][3] = fmaf(x1, wv.w, acc[1][3]);
        acc[2][0] = fmaf(x2, wv.x, acc[2][0]); acc[2][1] = fmaf(x2, wv.y, acc[2][1]);
        acc[2][2] = fmaf(x2, wv.z, acc[2][2]); acc[2][3] = fmaf(x2, wv.w, acc[2][3]);
        acc[3][0] = fmaf(x3, wv.x, acc[3][0]); acc[3][1] = fmaf(x3, wv.y, acc[3][1]);
        acc[3][2] = fmaf(x3, wv.z, acc[3][2]); acc[3][3] = fmaf(x3, wv.w, acc[3][3]);
    }

    const float* bg = bias + ((h * 2 + p) * 3 + k) * kDH;
    float4 bv = *reinterpret_cast<const float4*>(bg + tc * 4);
    const size_t obase = (size_t)k * kB * kH * kS * kDH
                       + ((size_t)b * kH + h) * kS * kDH + (size_t)s0 * kDH;
#pragma unroll
    for (int r = 0; r < 4; r++) {
        int row = tw + r * 8;
        float4 o = make_float4(acc[r][0] + bv.x, acc[r][1] + bv.y,
                               acc[r][2] + bv.z, acc[r][3] + bv.w);
        *reinterpret_cast<float4*>(&g_qkv[obase + (size_t)row * kDH + tc * 4]) = o;
    }
}

// ---------------------------------------------------------------------------
// tf32 mma.sync helpers
// ---------------------------------------------------------------------------
__device__ __forceinline__ unsigned f2tf(float f) {
    unsigned u; asm("cvt.rna.tf32.f32 %0, %1;" : "=r"(u) : "f"(f)); return u;
}
__device__ __forceinline__ void mma_tf32(
    float& d0, float& d1, float& d2, float& d3,
    unsigned a0, unsigned a1, unsigned a2, unsigned a3,
    unsigned b0, unsigned b1)
{
    asm("mma.sync.aligned.m16n8k8.row.col.f32.tf32.tf32.f32 "
        "{%0,%1,%2,%3},{%4,%5,%6,%7},{%8,%9},{%0,%1,%2,%3};"
        : "+f"(d0), "+f"(d1), "+f"(d2), "+f"(d3)
        : "r"(a0), "r"(a1), "r"(a2), "r"(a3), "r"(b0), "r"(b1));
}

// ---------------------------------------------------------------------------
// Kernel 2: tf32 tensor-core flash attention.
// Block: 256 threads (8 warps), Q tile 128 rows (warp w: rows w*16..w*16+15),
// K/V tile 64. Q/K/V staged in smem, tf32-rounded at stage.
// Row pads chosen for conflict-free fragment loads:
//   sQ/sK pad 132: lane addr = 132*r + c -> banks 4r+c (0..31, conflict-free)
//   sV    pad 136: lane addr = 136*c + r -> banks 8c+r (0..31, conflict-free)
// Scores S (16x64/warp) and O (16x128/warp) live in mma fragments.
// Online softmax is quad-local; P converted C-frag -> A-frag via 8 shfls/step.
// Fragment layouts (m16n8k8.tf32, r=lane>>2, c=lane&3):
//   A: a0=[r][c] a1=[r+8][c] a2=[r][c+4] a3=[r+8][c+4]
//   B: b0=[c][r'] b1=[c+4][r']            (col-major, r'=lane>>2)
//   D: d0=[r][2c] d1=[r][2c+1] d2=[r+8][2c] d3=[r+8][2c+1]
// ---------------------------------------------------------------------------
constexpr int QTT = 128, KTT = 64;
constexpr int LDQ = 132;    // sQ / sK row pitch (floats)
constexpr int LDV = 136;    // sV row pitch (floats)
constexpr int ATTN_SMEM_FLOATS = (QTT + KTT) * LDQ + KTT * LDV;
constexpr int ATTN_SMEM_BYTES  = ATTN_SMEM_FLOATS * 4;  // 136,192

__global__ __launch_bounds__(256, 1) void attn_kernel()
{
    extern __shared__ float smem[];
    float* sQ = smem;                       // [128][132]
    float* sK = smem + QTT * LDQ;           // [64][132]
    float* sV = sK + KTT * LDQ;             // [64][136]

    const int t = threadIdx.x, w = t >> 5, lane = t & 31;
    const int r = lane >> 2, c = lane & 3;
    const int qt = blockIdx.x, h = blockIdx.y, b = blockIdx.z;

    const size_t plane = (size_t)kS * kDH;
    const size_t base  = ((size_t)b * kH + h) * plane;
    const int    q0g   = qt * QTT;
    const float* Qp = g_qkv + base + (size_t)q0g * kDH;
    const float* Kp = g_qkv + (size_t)kB * kH * plane + base;
    const float* Vp = g_qkv + 2ull * kB * kH * plane + base;

    // stage Q tile (scaled + tf32-rounded): 128x128 -> sQ[row][col]
#pragma unroll
    for (int j = 0; j < 16; j++) {
        int i = t + j * 256;               // 0..4095 float4s
        int row = i >> 5, c4 = i & 31;
        float4 q = reinterpret_cast<const float4*>(Qp)[i];
        float4 o;
        o.x = __uint_as_float(f2tf(q.x * kScale));
        o.y = __uint_as_float(f2tf(q.y * kScale));
        o.z = __uint_as_float(f2tf(q.z * kScale));
        o.w = __uint_as_float(f2tf(q.w * kScale));
        *reinterpret_cast<float4*>(sQ + row * LDQ + c4 * 4) = o;
    }

    const int qr = w * 16;                 // warp's q-row base (local)

    float of[16][4];                       // O fragments: 16 rows x 128 cols
#pragma unroll
    for (int n = 0; n < 16; n++)
#pragma unroll
        for (int j = 0; j < 4; j++) of[n][j] = 0.f;
    float m0 = -INFINITY, m1 = -INFINITY, l0 = 0.f, l1 = 0.f;

    const int src1 = (lane & ~3) | (c >> 1);
    const int src2 = src1 | 2;
    const bool odd = (c & 1);

    for (int k0 = 0; k0 < kS; k0 += KTT) {
        __syncthreads();   // prior-iteration smem reads complete (covers sQ stage too)
        // stage K,V tiles (tf32-rounded): 64x128 each
        {
            const float4* Kg = reinterpret_cast<const float4*>(Kp + (size_t)k0 * kDH);
            const float4* Vg = reinterpret_cast<const float4*>(Vp + (size_t)k0 * kDH);
#pragma unroll
            for (int j = 0; j < 8; j++) {
                int i = t + j * 256;       // 0..2047 float4s
                int row = i >> 5, c4 = i & 31;
                float4 kq = Kg[i];
                float4 vq = Vg[i];
                float4 ko, vo;
                ko.x = __uint_as_float(f2tf(kq.x)); ko.y = __uint_as_float(f2tf(kq.y));
                ko.z = __uint_as_float(f2tf(kq.z)); ko.w = __uint_as_float(f2tf(kq.w));
                vo.x = __uint_as_float(f2tf(vq.x)); vo.y = __uint_as_float(f2tf(vq.y));
                vo.z = __uint_as_float(f2tf(vq.z)); vo.w = __uint_as_float(f2tf(vq.w));
                *reinterpret_cast<float4*>(sK + row * LDQ + c4 * 4) = ko;
                *reinterpret_cast<float4*>(sV + row * LDV + c4 * 4) = vo;
            }
        }
        __syncthreads();

        // ---- S = Q K^T : 16 k-steps (d), 8 n-tiles (keys) ----
        float sf[8][4];
#pragma unroll
        for (int n = 0; n < 8; n++)
#pragma unroll
            for (int j = 0; j < 4; j++) sf[n][j] = 0.f;

#pragma unroll
        for (int ks = 0; ks < 16; ks++) {
            const int d0 = ks * 8;
            const float* qa = sQ + (qr + r) * LDQ + d0 + c;
            unsigned a0 = __float_as_uint(qa[0]);
            unsigned a1 = __float_as_uint(qa[8 * LDQ]);
            unsigned a2 = __float_as_uint(qa[4]);
            unsigned a3 = __float_as_uint(qa[8 * LDQ + 4]);
#pragma unroll
            for (int n = 0; n < 8; n++) {
                const float* kb = sK + (n * 8 + r) * LDQ + d0 + c;
                unsigned b0 = __float_as_uint(kb[0]);
                unsigned b1 = __float_as_uint(kb[4]);
                mma_tf32(sf[n][0], sf[n][1], sf[n][2], sf[n][3],
                         a0, a1, a2, a3, b0, b1);
            }
        }

        // ---- online softmax (rows r and r+8 of this warp's 16) ----
        float rmax0 = -INFINITY, rmax1 = -INFINITY;
#pragma unroll
        for (int n = 0; n < 8; n++) {
            rmax0 = fmaxf(rmax0, fmaxf(sf[n][0], sf[n][1]));
            rmax1 = fmaxf(rmax1, fmaxf(sf[n][2], sf[n][3]));
        }
        rmax0 = fmaxf(rmax0, __shfl_xor_sync(0xffffffffu, rmax0, 1));
        rmax0 = fmaxf(rmax0, __shfl_xor_sync(0xffffffffu, rmax0, 2));
        rmax1 = fmaxf(rmax1, __shfl_xor_sync(0xffffffffu, rmax1, 1));
        rmax1 = fmaxf(rmax1, __shfl_xor_sync(0xffffffffu, rmax1, 2));
        float nm0 = fmaxf(m0, rmax0), nm1 = fmaxf(m1, rmax1);
        float c0 = __expf(m0 - nm0), c1 = __expf(m1 - nm1);
        m0 = nm0; m1 = nm1;

        float rs0 = 0.f, rs1 = 0.f;
#pragma unroll
        for (int n = 0; n < 8; n++) {
            sf[n][0] = __expf(sf[n][0] - m0);
            sf[n][1] = __expf(sf[n][1] - m0);
            sf[n][2] = __expf(sf[n][2] - m1);
            sf[n][3] = __expf(sf[n][3] - m1);
            rs0 += sf[n][0] + sf[n][1];
            rs1 += sf[n][2] + sf[n][3];
        }
        rs0 += __shfl_xor_sync(0xffffffffu, rs0, 1);
        rs0 += __shfl_xor_sync(0xffffffffu, rs0, 2);
        rs1 += __shfl_xor_sync(0xffffffffu, rs1, 1);
        rs1 += __shfl_xor_sync(0xffffffffu, rs1, 2);
        l0 = l0 * c0 + rs0;
        l1 = l1 * c1 + rs1;

#pragma unroll
        for (int n = 0; n < 16; n++) {
            of[n][0] *= c0; of[n][1] *= c0;
            of[n][2] *= c1; of[n][3] *= c1;
        }

        // ---- O += P @ V : 8 k-steps (keys), 16 n-tiles (dh) ----
#pragma unroll
        for (int ks = 0; ks < 8; ks++) {
            // C-frag -> A-frag conversion for P[16][ks*8..ks*8+7]
            float e0 = __shfl_sync(0xffffffffu, sf[ks][0], src1);
            float e1 = __shfl_sync(0xffffffffu, sf[ks][1], src1);
            float e2 = __shfl_sync(0xffffffffu, sf[ks][2], src1);
            float e3 = __shfl_sync(0xffffffffu, sf[ks][3], src1);
            float g0 = __shfl_sync(0xffffffffu, sf[ks][0], src2);
            float g1 = __shfl_sync(0xffffffffu, sf[ks][1], src2);
            float g2 = __shfl_sync(0xffffffffu, sf[ks][2], src2);
            float g3 = __shfl_sync(0xffffffffu, sf[ks][3], src2);
            unsigned a0 = f2tf(odd ? e1 : e0);   // [r][c]
            unsigned a1 = f2tf(odd ? e3 : e2);   // [r+8][c]
            unsigned a2 = f2tf(odd ? g1 : g0);   // [r][c+4]
            unsigned a3 = f2tf(odd ? g3 : g2);   // [r+8][c+4]
#pragma unroll
            for (int n = 0; n < 16; n++) {
                const float* vb = sV + (ks * 8 + c) * LDV + n * 8 + r;
                unsigned b0 = __float_as_uint(vb[0]);
                unsigned b1 = __float_as_uint(vb[4 * LDV]);
                mma_tf32(of[n][0], of[n][1], of[n][2], of[n][3],
                         a0, a1, a2, a3, b0, b1);
            }
        }
    }

    // ---- normalize + write O ----
    const float i0 = 1.f / l0, i1 = 1.f / l1;
    float* O = g_att + base + (size_t)q0g * kDH;
    const int row0 = qr + r, row1 = qr + r + 8;
#pragma unroll
    for (int n = 0; n < 16; n++) {
        int col = n * 8 + c * 2;
        *reinterpret_cast<float2*>(O + (size_t)row0 * kDH + col) =
            make_float2(of[n][0] * i0, of[n][1] * i0);
        *reinterpret_cast<float2*>(O + (size_t)row1 * kDH + col) =
            make_float2(of[n][2] * i1, of[n][3] * i1);
    }
}

// ---------------------------------------------------------------------------
// Kernel 3: out[b,s,:] = concat_h(O[b,h,s,:]) @ Wout + bout (unchanged)
// ---------------------------------------------------------------------------
__global__ __launch_bounds__(256) void out_kernel(
    const float* __restrict__ Wout, const float* __restrict__ bout,
    float* __restrict__ out)
{
    __shared__ float ws[64 * kDH];  // 32 KB
    __shared__ float xs[16 * 64];   // 4 KB

    const int t = threadIdx.x;
    const int row = t >> 4;
    const int dj  = t & 15;
    const int bs0 = blockIdx.x * 16;

    float acc[8];
#pragma unroll
    for (int j = 0; j < 8; j++) acc[j] = 0.f;

    for (int cch = 0; cch < 16; cch++) {
        const int i0 = cch * 64;
        __syncthreads();
        {
            const float4* Wsrc = reinterpret_cast<const float4*>(Wout + (size_t)i0 * kDH);
#pragma unroll
            for (int j = 0; j < 8; j++)
                reinterpret_cast<float4*>(ws)[t + j * 256] = Wsrc[t + j * 256];
        }
#pragma unroll
        for (int j = 0; j < 4; j++) {
            int i  = t + j * 256;
            int rr = i >> 6, ii = i & 63;
            int gi = i0 + ii;
            int hh = gi >> 7, e = gi & 127;
            int bs = bs0 + rr;
            int b  = bs / kS, s = bs % kS;
            xs[rr * 64 + ii] = g_att[(((size_t)b * kH + hh) * kS + s) * kDH + e];
        }
        __syncthreads();

#pragma unroll 8
        for (int ii = 0; ii < 64; ii++) {
            float xv = xs[row * 64 + ii];
#pragma unroll
            for (int j = 0; j < 8; j++)
                acc[j] = fmaf(xv, ws[ii * kDH + dj + 16 * j], acc[j]);
        }
    }

    const int bs = bs0 + row;
#pragma unroll
    for (int j = 0; j < 8; j++) {
        int d = dj + 16 * j;
        out[(size_t)bs * kDH + d] = acc[j] + bout[d];
    }
}

// ---------------------------------------------------------------------------
extern "C" void kernel_launch(void* const* d_in, const int* in_sizes, int n_in,
                              void* d_out, int out_size)
{
    (void)in_sizes; (void)n_in; (void)out_size;
    const float* f0   = (const float*)d_in[0];
    const float* u0   = (const float*)d_in[1];
    const float* f1   = (const float*)d_in[2];
    const float* u1   = (const float*)d_in[3];
    const float* Wf   = (const float*)d_in[4];
    const float* bf   = (const float*)d_in[5];
    const float* Wu   = (const float*)d_in[6];
    const float* bu   = (const float*)d_in[7];
    const float* Wout = (const float*)d_in[8];
    const float* bout = (const float*)d_in[9];
    float* out = (float*)d_out;

    // idempotent host-side attribute set; safe under graph capture
    cudaFuncSetAttribute(attn_kernel,
                         cudaFuncAttributeMaxDynamicSharedMemorySize, ATTN_SMEM_BYTES);

    proj_kernel<<<dim3(68, 3, kB * kH), 256>>>(f0, u0, f1, u1, Wf, bf, Wu, bu);
    attn_kernel<<<dim3(kS / QTT, kH, kB), 256, ATTN_SMEM_BYTES>>>();
    out_kernel<<<(kB * kS) / 16, 256>>>(Wout, bout, out);
}

// round 5
// speedup vs baseline: 3.8811x; 1.2448x over previous
#include <cuda_runtime.h>
#include <math.h>

// ---------------------------------------------------------------------------
// FourSequenceMHAttention: B=8, H=8, S=2176 (64+1024+64+1024), DH=128
// k1: tiled QKV projection (W staged in smem) -> g_qkv[3][B][H][S][DH]
// k2: bf16 m16n8k16 mma.sync flash attention  -> g_att[B][H][S][DH]
// k3: output projection (H*DH -> DH) + bias   -> out[B][S][DH]
// ---------------------------------------------------------------------------

namespace cfg {
constexpr int kB = 8, kH = 8, kNF = 64, kNU = 1024;
constexpr int kS = 2176, kDF = 64, kDU = 32, kDH = 128;
constexpr float kScale = 0.08838834764831845f;   // 1/sqrt(128)
}
using namespace cfg;

// Scratch (device globals: allocation-free per harness rules)
__device__ float g_qkv[3ull * kB * kH * kS * kDH];   // ~214 MB
__device__ float g_att[(size_t)kB * kH * kS * kDH];  // ~71 MB

// ---------------------------------------------------------------------------
// Kernel 1: QKV projection as a tiled GEMM (measured: 110us, passing)
// ---------------------------------------------------------------------------
__global__ __launch_bounds__(256) void proj_kernel(
    const float* __restrict__ f0, const float* __restrict__ u0,
    const float* __restrict__ f1, const float* __restrict__ u1,
    const float* __restrict__ Wf, const float* __restrict__ bf,
    const float* __restrict__ Wu, const float* __restrict__ bu)
{
    __shared__ float sW[kDF * kDH];   // up to 64 x 128 = 32KB
    __shared__ float sx[32 * kDF];    // 32 rows x Din    = 8KB max

    const int tile = blockIdx.x;      // 0..67 (32-row s-tiles)
    const int k    = blockIdx.y;      // 0..2 (q/k/v)
    const int bh   = blockIdx.z;
    const int b = bh >> 3, h = bh & 7;

    const float* x; const float* W; const float* bias;
    int Din, p, s0, n0, rows;
    if (tile < 2)       { x=f0; W=Wf; bias=bf; Din=kDF; p=0; n0=tile*32;      s0=n0;              rows=kNF; }
    else if (tile < 34) { x=u0; W=Wu; bias=bu; Din=kDU; p=0; n0=(tile-2)*32;  s0=kNF+n0;          rows=kNU; }
    else if (tile < 36) { x=f1; W=Wf; bias=bf; Din=kDF; p=1; n0=(tile-34)*32; s0=kNF+kNU+n0;      rows=kNF; }
    else                { x=u1; W=Wu; bias=bu; Din=kDU; p=1; n0=(tile-36)*32; s0=2*kNF+kNU+n0;    rows=kNU; }

    const int t = threadIdx.x;

    const float* Wg = W + (size_t)(((h * 2 + p) * 3 + k) * Din) * kDH;
    for (int i = t; i < Din * kDH / 4; i += 256)
        reinterpret_cast<float4*>(sW)[i] = reinterpret_cast<const float4*>(Wg)[i];
    const float* xg = x + ((size_t)b * rows + n0) * Din;
    for (int i = t; i < 32 * Din / 4; i += 256)
        reinterpret_cast<float4*>(sx)[i] = reinterpret_cast<const float4*>(xg)[i];
    __syncthreads();

    const int tw = t >> 5;
    const int tc = t & 31;

    float acc[4][4];
#pragma unroll
    for (int i = 0; i < 4; i++)
#pragma unroll
        for (int j = 0; j < 4; j++) acc[i][j] = 0.f;

#pragma unroll 4
    for (int f = 0; f < Din; f++) {
        float4 wv = *reinterpret_cast<const float4*>(sW + f * kDH + tc * 4);
        float x0 = sx[(tw     ) * Din + f];
        float x1 = sx[(tw +  8) * Din + f];
        float x2 = sx[(tw + 16) * Din + f];
        float x3 = sx[(tw + 24) * Din + f];
        acc[0][0] = fmaf(x0, wv.x, acc[0][0]); acc[0][1] = fmaf(x0, wv.y, acc[0][1]);
        acc[0][2] = fmaf(x0, wv.z, acc[0][2]); acc[0][3] = fmaf(x0, wv.w, acc[0][3]);
        acc[1][0] = fmaf(x1, wv.x, acc[1][0]); acc[1][1] = fmaf(x1, wv.y, acc[1][1]);
        acc[1][2] = fmaf(x1, wv.z, acc[1][2]); acc[1][3] = fmaf(x1, wv.w, acc[1][3]);
        acc[2][0] = fmaf(x2, wv.x, acc[2][0]); acc[2][1] = fmaf(x2, wv.y, acc[2][1]);
        acc[2][2] = fmaf(x2, wv.z, acc[2][2]); acc[2][3] = fmaf(x2, wv.w, acc[2][3]);
        acc[3][0] = fmaf(x3, wv.x, acc[3][0]); acc[3][1] = fmaf(x3, wv.y, acc[3][1]);
        acc[3][2] = fmaf(x3, wv.z, acc[3][2]); acc[3][3] = fmaf(x3, wv.w, acc[3][3]);
    }

    const float* bg = bias + ((h * 2 + p) * 3 + k) * kDH;
    float4 bv = *reinterpret_cast<const float4*>(bg + tc * 4);
    const size_t obase = (size_t)k * kB * kH * kS * kDH
                       + ((size_t)b * kH + h) * kS * kDH + (size_t)s0 * kDH;
#pragma unroll
    for (int r = 0; r < 4; r++) {
        int row = tw + r * 8;
        float4 o = make_float4(acc[r][0] + bv.x, acc[r][1] + bv.y,
                               acc[r][2] + bv.z, acc[r][3] + bv.w);
        *reinterpret_cast<float4*>(&g_qkv[obase + (size_t)row * kDH + tc * 4]) = o;
    }
}

// ---------------------------------------------------------------------------
// bf16 mma.sync helpers
// ---------------------------------------------------------------------------
__device__ __forceinline__ unsigned pack_bf(float lo, float hi) {
    unsigned r;  // cvt.bf16x2: first src -> upper half, second src -> lower
    asm("cvt.rn.bf16x2.f32 %0, %1, %2;" : "=r"(r) : "f"(hi), "f"(lo));
    return r;
}
__device__ __forceinline__ void mma_bf16(
    float& d0, float& d1, float& d2, float& d3,
    unsigned a0, unsigned a1, unsigned a2, unsigned a3,
    unsigned b0, unsigned b1)
{
    asm("mma.sync.aligned.m16n8k16.row.col.f32.bf16.bf16.f32 "
        "{%0,%1,%2,%3},{%4,%5,%6,%7},{%8,%9},{%0,%1,%2,%3};"
        : "+f"(d0), "+f"(d1), "+f"(d2), "+f"(d3)
        : "r"(a0), "r"(a1), "r"(a2), "r"(a3), "r"(b0), "r"(b1));
}

// ---------------------------------------------------------------------------
// Kernel 2: bf16 tensor-core flash attention.
// Block: 256 threads (8 warps), Q tile 128 rows (warp w: rows w*16..w*16+15),
// K/V tile 64. Storage (32-bit words = bf16x2):
//   sQ/sK rows [row][dh/2], pitch 68 words -> frag loads hit banks 4r+c (free)
//   sVt key-pair transposed [dh][keypair],  pitch 36 words -> banks 4r+c (free)
// Scores S (16x64/warp, f32 frags) and O (16x128/warp) live in registers.
// P(f32 C-frags) -> bf16 A-frags by direct packing (no shuffles):
//   k16 A chunk ks: a0=pack(d0,d1)|tile 2ks, a1=pack(d2,d3)|tile 2ks,
//                   a2=pack(d0,d1)|tile 2ks+1, a3=pack(d2,d3)|tile 2ks+1.
// Fragment maps (r=lane>>2, c=lane&3):
//   A: a0=[r][2c,2c+1] a1=[r+8][2c,2c+1] a2=[r][2c+8,2c+9] a3=[r+8][2c+8,2c+9]
//   B: b0={B[2c],B[2c+1]}@col r'  b1={B[2c+8],B[2c+9]}@col r'
//   C: d0=[r][2c] d1=[r][2c+1] d2=[r+8][2c] d3=[r+8][2c+1]
// Smem 70,656B -> 2 blocks/SM (staging overlaps compute across blocks).
// ---------------------------------------------------------------------------
constexpr int QTT = 128, KTT = 64;
constexpr int LDKW = 68;   // Q/K row pitch in 32-bit words (64 + 4 pad)
constexpr int LDVW = 36;   // sVt row pitch in 32-bit words (32 + 4 pad)
constexpr int SQ_WORDS = QTT * LDKW;           // 8704
constexpr int SK_WORDS = KTT * LDKW;           // 4352
constexpr int SV_WORDS = kDH * LDVW;           // 4608
constexpr int ATTN_SMEM_BYTES = (SQ_WORDS + SK_WORDS + SV_WORDS) * 4;  // 70,656

__global__ __launch_bounds__(256, 2) void attn_kernel()
{
    extern __shared__ unsigned usmem[];
    unsigned* uq  = usmem;                 // [128][68]
    unsigned* uk  = usmem + SQ_WORDS;      // [64][68]
    unsigned* uvt = uk + SK_WORDS;         // [128][36]

    const int t = threadIdx.x, w = t >> 5, lane = t & 31;
    const int r = lane >> 2, c = lane & 3;
    const int qt = blockIdx.x, h = blockIdx.y, b = blockIdx.z;

    const size_t plane = (size_t)kS * kDH;
    const size_t base  = ((size_t)b * kH + h) * plane;
    const int    q0g   = qt * QTT;
    const float* Qp = g_qkv + base + (size_t)q0g * kDH;
    const float* Kp = g_qkv + (size_t)kB * kH * plane + base;
    const float* Vp = g_qkv + 2ull * kB * kH * plane + base;

    // stage Q tile (scaled -> bf16): 128x128 -> uq[row][dh/2]
#pragma unroll
    for (int j = 0; j < 16; j++) {
        int i = t + j * 256;               // 0..4095 float4s (32 per row)
        int row = i >> 5, c4 = i & 31;
        float4 q = reinterpret_cast<const float4*>(Qp)[i];
        uint2 o;
        o.x = pack_bf(q.x * kScale, q.y * kScale);
        o.y = pack_bf(q.z * kScale, q.w * kScale);
        *reinterpret_cast<uint2*>(uq + row * LDKW + c4 * 2) = o;
    }

    const int qr = w * 16;                 // warp's q-row base (local)

    float of[16][4];
#pragma unroll
    for (int n = 0; n < 16; n++)
#pragma unroll
        for (int j = 0; j < 4; j++) of[n][j] = 0.f;
    float m0 = -INFINITY, m1 = -INFINITY, l0 = 0.f, l1 = 0.f;

    for (int k0 = 0; k0 < kS; k0 += KTT) {
        __syncthreads();   // prior-iteration smem reads complete (covers sQ stage)
        // stage K tile: 64x128 -> uk[row][dh/2]
        {
            const float4* Kg = reinterpret_cast<const float4*>(Kp + (size_t)k0 * kDH);
#pragma unroll
            for (int j = 0; j < 8; j++) {
                int i = t + j * 256;       // 0..2047
                int row = i >> 5, c4 = i & 31;
                float4 kq = Kg[i];
                uint2 o;
                o.x = pack_bf(kq.x, kq.y);
                o.y = pack_bf(kq.z, kq.w);
                *reinterpret_cast<uint2*>(uk + row * LDKW + c4 * 2) = o;
            }
        }
        // stage V tile key-pair transposed: uvt[dh][kp] = {V[2kp][dh], V[2kp+1][dh]}
        {
            const float4* Vg = reinterpret_cast<const float4*>(Vp + (size_t)k0 * kDH);
#pragma unroll
            for (int j = 0; j < 4; j++) {
                int i = t + j * 256;       // 0..1023
                int kp = i & 31, dq = i >> 5;   // keypair, dh-quad
                float4 v0 = Vg[(2 * kp    ) * 32 + dq];
                float4 v1 = Vg[(2 * kp + 1) * 32 + dq];
                uvt[(dq * 4 + 0) * LDVW + kp] = pack_bf(v0.x, v1.x);
                uvt[(dq * 4 + 1) * LDVW + kp] = pack_bf(v0.y, v1.y);
                uvt[(dq * 4 + 2) * LDVW + kp] = pack_bf(v0.z, v1.z);
                uvt[(dq * 4 + 3) * LDVW + kp] = pack_bf(v0.w, v1.w);
            }
        }
        __syncthreads();

        // ---- S = Q K^T : 8 k16-steps (dh), 8 n-tiles (keys) ----
        float sf[8][4];
#pragma unroll
        for (int n = 0; n < 8; n++)
#pragma unroll
            for (int j = 0; j < 4; j++) sf[n][j] = 0.f;

#pragma unroll
        for (int ks = 0; ks < 8; ks++) {
            const unsigned* qa = uq + (qr + r) * LDKW + ks * 8 + c;
            unsigned a0 = qa[0];
            unsigned a1 = qa[8 * LDKW];
            unsigned a2 = qa[4];
            unsigned a3 = qa[8 * LDKW + 4];
#pragma unroll
            for (int n = 0; n < 8; n++) {
                const unsigned* kb = uk + (n * 8 + r) * LDKW + ks * 8 + c;
                mma_bf16(sf[n][0], sf[n][1], sf[n][2], sf[n][3],
                         a0, a1, a2, a3, kb[0], kb[4]);
            }
        }

        // ---- online softmax (rows r and r+8 of this warp's 16) ----
        float rmax0 = -INFINITY, rmax1 = -INFINITY;
#pragma unroll
        for (int n = 0; n < 8; n++) {
            rmax0 = fmaxf(rmax0, fmaxf(sf[n][0], sf[n][1]));
            rmax1 = fmaxf(rmax1, fmaxf(sf[n][2], sf[n][3]));
        }
        rmax0 = fmaxf(rmax0, __shfl_xor_sync(0xffffffffu, rmax0, 1));
        rmax0 = fmaxf(rmax0, __shfl_xor_sync(0xffffffffu, rmax0, 2));
        rmax1 = fmaxf(rmax1, __shfl_xor_sync(0xffffffffu, rmax1, 1));
        rmax1 = fmaxf(rmax1, __shfl_xor_sync(0xffffffffu, rmax1, 2));
        float nm0 = fmaxf(m0, rmax0), nm1 = fmaxf(m1, rmax1);
        float c0 = __expf(m0 - nm0), c1 = __expf(m1 - nm1);
        m0 = nm0; m1 = nm1;

        float rs0 = 0.f, rs1 = 0.f;
#pragma unroll
        for (int n = 0; n < 8; n++) {
            sf[n][0] = __expf(sf[n][0] - m0);
            sf[n][1] = __expf(sf[n][1] - m0);
            sf[n][2] = __expf(sf[n][2] - m1);
            sf[n][3] = __expf(sf[n][3] - m1);
            rs0 += sf[n][0] + sf[n][1];
            rs1 += sf[n][2] + sf[n][3];
        }
        rs0 += __shfl_xor_sync(0xffffffffu, rs0, 1);
        rs0 += __shfl_xor_sync(0xffffffffu, rs0, 2);
        rs1 += __shfl_xor_sync(0xffffffffu, rs1, 1);
        rs1 += __shfl_xor_sync(0xffffffffu, rs1, 2);
        l0 = l0 * c0 + rs0;
        l1 = l1 * c1 + rs1;

#pragma unroll
        for (int n = 0; n < 16; n++) {
            of[n][0] *= c0; of[n][1] *= c0;
            of[n][2] *= c1; of[n][3] *= c1;
        }

        // ---- O += P @ V : 4 k16-steps (keys), 16 n-tiles (dh) ----
#pragma unroll
        for (int ks = 0; ks < 4; ks++) {
            unsigned a0 = pack_bf(sf[2*ks    ][0], sf[2*ks    ][1]);
            unsigned a1 = pack_bf(sf[2*ks    ][2], sf[2*ks    ][3]);
            unsigned a2 = pack_bf(sf[2*ks + 1][0], sf[2*ks + 1][1]);
            unsigned a3 = pack_bf(sf[2*ks + 1][2], sf[2*ks + 1][3]);
#pragma unroll
            for (int n = 0; n < 16; n++) {
                const unsigned* vb = uvt + (n * 8 + r) * LDVW + ks * 8 + c;
                mma_bf16(of[n][0], of[n][1], of[n][2], of[n][3],
                         a0, a1, a2, a3, vb[0], vb[4]);
            }
        }
    }

    // ---- normalize + write O ----
    const float i0 = 1.f / l0, i1 = 1.f / l1;
    float* O = g_att + base + (size_t)q0g * kDH;
    const int row0 = qr + r, row1 = qr + r + 8;
#pragma unroll
    for (int n = 0; n < 16; n++) {
        int col = n * 8 + c * 2;
        *reinterpret_cast<float2*>(O + (size_t)row0 * kDH + col) =
            make_float2(of[n][0] * i0, of[n][1] * i0);
        *reinterpret_cast<float2*>(O + (size_t)row1 * kDH + col) =
            make_float2(of[n][2] * i1, of[n][3] * i1);
    }
}

// ---------------------------------------------------------------------------
// Kernel 3: out[b,s,:] = concat_h(O[b,h,s,:]) @ Wout + bout (unchanged)
// ---------------------------------------------------------------------------
__global__ __launch_bounds__(256) void out_kernel(
    const float* __restrict__ Wout, const float* __restrict__ bout,
    float* __restrict__ out)
{
    __shared__ float ws[64 * kDH];  // 32 KB
    __shared__ float xs[16 * 64];   // 4 KB

    const int t = threadIdx.x;
    const int row = t >> 4;
    const int dj  = t & 15;
    const int bs0 = blockIdx.x * 16;

    float acc[8];
#pragma unroll
    for (int j = 0; j < 8; j++) acc[j] = 0.f;

    for (int cch = 0; cch < 16; cch++) {
        const int i0 = cch * 64;
        __syncthreads();
        {
            const float4* Wsrc = reinterpret_cast<const float4*>(Wout + (size_t)i0 * kDH);
#pragma unroll
            for (int j = 0; j < 8; j++)
                reinterpret_cast<float4*>(ws)[t + j * 256] = Wsrc[t + j * 256];
        }
#pragma unroll
        for (int j = 0; j < 4; j++) {
            int i  = t + j * 256;
            int rr = i >> 6, ii = i & 63;
            int gi = i0 + ii;
            int hh = gi >> 7, e = gi & 127;
            int bs = bs0 + rr;
            int b  = bs / kS, s = bs % kS;
            xs[rr * 64 + ii] = g_att[(((size_t)b * kH + hh) * kS + s) * kDH + e];
        }
        __syncthreads();

#pragma unroll 8
        for (int ii = 0; ii < 64; ii++) {
            float xv = xs[row * 64 + ii];
#pragma unroll
            for (int j = 0; j < 8; j++)
                acc[j] = fmaf(xv, ws[ii * kDH + dj + 16 * j], acc[j]);
        }
    }

    const int bs = bs0 + row;
#pragma unroll
    for (int j = 0; j < 8; j++) {
        int d = dj + 16 * j;
        out[(size_t)bs * kDH + d] = acc[j] + bout[d];
    }
}

// ---------------------------------------------------------------------------
extern "C" void kernel_launch(void* const* d_in, const int* in_sizes, int n_in,
                              void* d_out, int out_size)
{
    (void)in_sizes; (void)n_in; (void)out_size;
    const float* f0   = (const float*)d_in[0];
    const float* u0   = (const float*)d_in[1];
    const float* f1   = (const float*)d_in[2];
    const float* u1   = (const float*)d_in[3];
    const float* Wf   = (const float*)d_in[4];
    const float* bf   = (const float*)d_in[5];
    const float* Wu   = (const float*)d_in[6];
    const float* bu   = (const float*)d_in[7];
    const float* Wout = (const float*)d_in[8];
    const float* bout = (const float*)d_in[9];
    float* out = (float*)d_out;

    // idempotent host-side attribute set; safe under graph capture
    cudaFuncSetAttribute(attn_kernel,
                         cudaFuncAttributeMaxDynamicSharedMemorySize, ATTN_SMEM_BYTES);

    proj_kernel<<<dim3(68, 3, kB * kH), 256>>>(f0, u0, f1, u1, Wf, bf, Wu, bu);
    attn_kernel<<<dim3(kS / QTT, kH, kB), 256, ATTN_SMEM_BYTES>>>();
    out_kernel<<<(kB * kS) / 16, 256>>>(Wout, bout, out);
}

// round 16
// speedup vs baseline: 5.2191x; 1.3447x over previous
#include <cuda_runtime.h>
#include <math.h>

// ---------------------------------------------------------------------------
// FourSequenceMHAttention: B=8, H=8, S=2176 (64+1024+64+1024), DH=128
// k1: proj -> bf16 Q(prescaled)/K rows + V packed key-pair-transposed
// k2: bf16 m16n8k16 flash attention, cp.async double-buffered staging
// k3: output projection (H*DH -> DH) + bias -> out[B][S][DH]
// ---------------------------------------------------------------------------

namespace cfg {
constexpr int kB = 8, kH = 8, kNF = 64, kNU = 1024;
constexpr int kS = 2176, kDF = 64, kDU = 32, kDH = 128;
constexpr int kSW = kDH / 2;        // 64 words per bf16 row
constexpr int kKP = kS / 2;         // 1088 keypairs
constexpr float kScale = 0.08838834764831845f;   // 1/sqrt(128)
}
using namespace cfg;

// Scratch (device globals: allocation-free per harness rules)
__device__ unsigned g_qbf[(size_t)kB * kH * kS * kSW];   // Q bf16x2, prescaled
__device__ unsigned g_kbf[(size_t)kB * kH * kS * kSW];   // K bf16x2 rows
__device__ unsigned g_vt [(size_t)kB * kH * kDH * kKP];  // V^T: [bh][dh][kp]
__device__ float    g_att[(size_t)kB * kH * kS * kDH];   // attention out (f32)

// ---------------------------------------------------------------------------
// helpers
// ---------------------------------------------------------------------------
__device__ __forceinline__ unsigned pack_bf(float lo, float hi) {
    unsigned r;  // first src -> upper half, second -> lower
    asm("cvt.rn.bf16x2.f32 %0, %1, %2;" : "=r"(r) : "f"(hi), "f"(lo));
    return r;
}
__device__ __forceinline__ void mma_bf16(
    float& d0, float& d1, float& d2, float& d3,
    unsigned a0, unsigned a1, unsigned a2, unsigned a3,
    unsigned b0, unsigned b1)
{
    asm("mma.sync.aligned.m16n8k16.row.col.f32.bf16.bf16.f32 "
        "{%0,%1,%2,%3},{%4,%5,%6,%7},{%8,%9},{%0,%1,%2,%3};"
        : "+f"(d0), "+f"(d1), "+f"(d2), "+f"(d3)
        : "r"(a0), "r"(a1), "r"(a2), "r"(a3), "r"(b0), "r"(b1));
}
__device__ __forceinline__ void cp16(unsigned* dst_smem, const unsigned* src_gmem) {
    unsigned s = (unsigned)__cvta_generic_to_shared(dst_smem);
    asm volatile("cp.async.cg.shared.global [%0], [%1], 16;" :: "r"(s), "l"(src_gmem));
}
__device__ __forceinline__ void cp_commit() {
    asm volatile("cp.async.commit_group;");
}

// ---------------------------------------------------------------------------
// Kernel 1: QKV projection (tiled GEMM) -> bf16 outputs.
//   k=0: Q rows, (acc+bias)*kScale, bf16x2 words
//   k=1: K rows, bf16x2 words
//   k=2: V -> stage tile in smem, write packed key-pair transposed g_vt
// ---------------------------------------------------------------------------
__global__ __launch_bounds__(256) void proj_kernel(
    const float* __restrict__ f0, const float* __restrict__ u0,
    const float* __restrict__ f1, const float* __restrict__ u1,
    const float* __restrict__ Wf, const float* __restrict__ bf,
    const float* __restrict__ Wu, const float* __restrict__ bu)
{
    __shared__ float sW[kDF * kDH];   // 32KB (reused as V staging buffer)
    __shared__ float sx[32 * kDF];    // 8KB

    const int tile = blockIdx.x;      // 0..67 (32-row s-tiles)
    const int k    = blockIdx.y;      // 0..2 (q/k/v)
    const int bh   = blockIdx.z;
    const int b = bh >> 3, h = bh & 7;

    const float* x; const float* W; const float* bias;
    int Din, p, s0, n0, rows;
    if (tile < 2)       { x=f0; W=Wf; bias=bf; Din=kDF; p=0; n0=tile*32;      s0=n0;              rows=kNF; }
    else if (tile < 34) { x=u0; W=Wu; bias=bu; Din=kDU; p=0; n0=(tile-2)*32;  s0=kNF+n0;          rows=kNU; }
    else if (tile < 36) { x=f1; W=Wf; bias=bf; Din=kDF; p=1; n0=(tile-34)*32; s0=kNF+kNU+n0;      rows=kNF; }
    else                { x=u1; W=Wu; bias=bu; Din=kDU; p=1; n0=(tile-36)*32; s0=2*kNF+kNU+n0;    rows=kNU; }

    const int t = threadIdx.x;

    const float* Wg = W + (size_t)(((h * 2 + p) * 3 + k) * Din) * kDH;
    for (int i = t; i < Din * kDH / 4; i += 256)
        reinterpret_cast<float4*>(sW)[i] = reinterpret_cast<const float4*>(Wg)[i];
    const float* xg = x + ((size_t)b * rows + n0) * Din;
    for (int i = t; i < 32 * Din / 4; i += 256)
        reinterpret_cast<float4*>(sx)[i] = reinterpret_cast<const float4*>(xg)[i];
    __syncthreads();

    const int tw = t >> 5;   // rows tw, tw+8, tw+16, tw+24
    const int tc = t & 31;   // cols tc*4..tc*4+3

    float acc[4][4];
#pragma unroll
    for (int i = 0; i < 4; i++)
#pragma unroll
        for (int j = 0; j < 4; j++) acc[i][j] = 0.f;

#pragma unroll 4
    for (int f = 0; f < Din; f++) {
        float4 wv = *reinterpret_cast<const float4*>(sW + f * kDH + tc * 4);
        float x0 = sx[(tw     ) * Din + f];
        float x1 = sx[(tw +  8) * Din + f];
        float x2 = sx[(tw + 16) * Din + f];
        float x3 = sx[(tw + 24) * Din + f];
        acc[0][0] = fmaf(x0, wv.x, acc[0][0]); acc[0][1] = fmaf(x0, wv.y, acc[0][1]);
        acc[0][2] = fmaf(x0, wv.z, acc[0][2]); acc[0][3] = fmaf(x0, wv.w, acc[0][3]);
        acc[1][0] = fmaf(x1, wv.x, acc[1][0]); acc[1][1] = fmaf(x1, wv.y, acc[1][1]);
        acc[1][2] = fmaf(x1, wv.z, acc[1][2]); acc[1][3] = fmaf(x1, wv.w, acc[1][3]);
        acc[2][0] = fmaf(x2, wv.x, acc[2][0]); acc[2][1] = fmaf(x2, wv.y, acc[2][1]);
        acc[2][2] = fmaf(x2, wv.z, acc[2][2]); acc[2][3] = fmaf(x2, wv.w, acc[2][3]);
        acc[3][0] = fmaf(x3, wv.x, acc[3][0]); acc[3][1] = fmaf(x3, wv.y, acc[3][1]);
        acc[3][2] = fmaf(x3, wv.z, acc[3][2]); acc[3][3] = fmaf(x3, wv.w, acc[3][3]);
    }

    const float* bg = bias + ((h * 2 + p) * 3 + k) * kDH;
    float4 bv = *reinterpret_cast<const float4*>(bg + tc * 4);

    if (k < 2) {
        // Q (prescaled) / K : bf16x2 rows
        const float sc = (k == 0) ? kScale : 1.0f;
        unsigned* dst = (k == 0 ? g_qbf : g_kbf) + ((size_t)bh * kS + s0) * kSW;
#pragma unroll
        for (int r = 0; r < 4; r++) {
            int row = tw + r * 8;
            uint2 o;
            o.x = pack_bf((acc[r][0] + bv.x) * sc, (acc[r][1] + bv.y) * sc);
            o.y = pack_bf((acc[r][2] + bv.z) * sc, (acc[r][3] + bv.w) * sc);
            *reinterpret_cast<uint2*>(dst + (size_t)row * kSW + tc * 2) = o;
        }
    } else {
        // V: stage fp32 tile [32][128] (pitch 129) in sW, then packed transpose
        float* sv = sW;
        __syncthreads();   // everyone done reading sW
#pragma unroll
        for (int r = 0; r < 4; r++) {
            int row = tw + r * 8;
            sv[row * 129 + tc * 4 + 0] = acc[r][0] + bv.x;
            sv[row * 129 + tc * 4 + 1] = acc[r][1] + bv.y;
            sv[row * 129 + tc * 4 + 2] = acc[r][2] + bv.z;
            sv[row * 129 + tc * 4 + 3] = acc[r][3] + bv.w;
        }
        __syncthreads();
        unsigned* dst = g_vt + (size_t)bh * kDH * kKP + (s0 >> 1);
#pragma unroll
        for (int idx = t; idx < 128 * 16; idx += 256) {
            int d = idx >> 4, j = idx & 15;          // dh row, local keypair
            float v0 = sv[(2 * j    ) * 129 + d];
            float v1 = sv[(2 * j + 1) * 129 + d];
            dst[(size_t)d * kKP + j] = pack_bf(v0, v1);
        }
    }
}

// ---------------------------------------------------------------------------
// Kernel 2: bf16 tensor-core flash attention, cp.async double-buffered.
// Block: 256 threads (8 warps), Q tile 128 rows, K/V tile 64 keys.
// smem (32-bit words): uq[128][68], uk[2][64][68], uvt[2][128][36]
// Fragment maps identical to R5 (measured correct, bank-conflict-free).
// Pipeline: prologue {Q + K0 + V0} commit; loop: issue(i+1), wait<=1, sync,
// compute(i), sync.
// ---------------------------------------------------------------------------
constexpr int QTT = 128, KTT = 64;
constexpr int LDKW = 68;   // Q/K smem row pitch (words)
constexpr int LDVW = 36;   // V^T smem row pitch (words)
constexpr int SQ_WORDS = QTT * LDKW;           // 8704
constexpr int SK_WORDS = KTT * LDKW;           // 4352
constexpr int SV_WORDS = kDH * LDVW;           // 4608
constexpr int ATTN_SMEM_BYTES = (SQ_WORDS + 2 * SK_WORDS + 2 * SV_WORDS) * 4; // 106,496
constexpr int NT = kS / KTT;                   // 34 tiles

__global__ __launch_bounds__(256, 2) void attn_kernel()
{
    extern __shared__ unsigned usmem[];
    unsigned* uq  = usmem;                        // [128][68]
    unsigned* uk0 = usmem + SQ_WORDS;             // [64][68] buf0
    unsigned* uk1 = uk0 + SK_WORDS;               // buf1
    unsigned* uv0 = uk1 + SK_WORDS;               // [128][36] buf0
    unsigned* uv1 = uv0 + SV_WORDS;               // buf1

    const int t = threadIdx.x, w = t >> 5, lane = t & 31;
    const int r = lane >> 2, c = lane & 3;
    const int qt = blockIdx.x, bh = blockIdx.y;   // bh = b*8+h

    const int q0g = qt * QTT;
    const unsigned* Qg = g_qbf + ((size_t)bh * kS + q0g) * kSW;
    const unsigned* Kg = g_kbf + (size_t)bh * kS * kSW;
    const unsigned* Vg = g_vt  + (size_t)bh * kDH * kKP;

    // ---- prologue: Q + K0 + V0 in one cp.async group ----
#pragma unroll
    for (int j = 0; j < 8; j++) {                 // Q: 2048 16B-chunks
        int i = t + j * 256;
        int row = i >> 4, col = i & 15;
        cp16(uq + row * LDKW + col * 4, Qg + row * kSW + col * 4);
    }
#pragma unroll
    for (int j = 0; j < 4; j++) {                 // K0: 1024 chunks
        int i = t + j * 256;
        int row = i >> 4, col = i & 15;
        cp16(uk0 + row * LDKW + col * 4, Kg + row * kSW + col * 4);
    }
#pragma unroll
    for (int j = 0; j < 4; j++) {                 // V0: 1024 chunks
        int i = t + j * 256;
        int row = i >> 3, col = i & 7;
        cp16(uv0 + row * LDVW + col * 4, Vg + (size_t)row * kKP + col * 4);
    }
    cp_commit();

    const int qr = w * 16;

    float of[16][4];
#pragma unroll
    for (int n = 0; n < 16; n++)
#pragma unroll
        for (int j = 0; j < 4; j++) of[n][j] = 0.f;
    float m0 = -INFINITY, m1 = -INFINITY, l0 = 0.f, l1 = 0.f;

    for (int it = 0; it < NT; it++) {
        // issue next tile into the other buffer
        if (it + 1 < NT) {
            unsigned* ukn = (it & 1) ? uk0 : uk1;
            unsigned* uvn = (it & 1) ? uv0 : uv1;
            const unsigned* Kn = Kg + (size_t)(it + 1) * KTT * kSW;
            const unsigned* Vn = Vg + (size_t)(it + 1) * (KTT / 2);
#pragma unroll
            for (int j = 0; j < 4; j++) {
                int i = t + j * 256;
                int row = i >> 4, col = i & 15;
                cp16(ukn + row * LDKW + col * 4, Kn + row * kSW + col * 4);
            }
#pragma unroll
            for (int j = 0; j < 4; j++) {
                int i = t + j * 256;
                int row = i >> 3, col = i & 7;
                cp16(uvn + row * LDVW + col * 4, Vn + (size_t)row * kKP + col * 4);
            }
            cp_commit();
            asm volatile("cp.async.wait_group 1;");
        } else {
            asm volatile("cp.async.wait_group 0;");
        }
        __syncthreads();   // tile `it` visible to all

        const unsigned* ukc = (it & 1) ? uk1 : uk0;
        const unsigned* uvc = (it & 1) ? uv1 : uv0;

        // ---- S = Q K^T : 8 k16-steps (dh), 8 n-tiles (keys) ----
        float sf[8][4];
#pragma unroll
        for (int n = 0; n < 8; n++)
#pragma unroll
            for (int j = 0; j < 4; j++) sf[n][j] = 0.f;

#pragma unroll
        for (int ks = 0; ks < 8; ks++) {
            const unsigned* qa = uq + (qr + r) * LDKW + ks * 8 + c;
            unsigned a0 = qa[0];
            unsigned a1 = qa[8 * LDKW];
            unsigned a2 = qa[4];
            unsigned a3 = qa[8 * LDKW + 4];
#pragma unroll
            for (int n = 0; n < 8; n++) {
                const unsigned* kb = ukc + (n * 8 + r) * LDKW + ks * 8 + c;
                mma_bf16(sf[n][0], sf[n][1], sf[n][2], sf[n][3],
                         a0, a1, a2, a3, kb[0], kb[4]);
            }
        }

        // ---- online softmax ----
        float rmax0 = -INFINITY, rmax1 = -INFINITY;
#pragma unroll
        for (int n = 0; n < 8; n++) {
            rmax0 = fmaxf(rmax0, fmaxf(sf[n][0], sf[n][1]));
            rmax1 = fmaxf(rmax1, fmaxf(sf[n][2], sf[n][3]));
        }
        rmax0 = fmaxf(rmax0, __shfl_xor_sync(0xffffffffu, rmax0, 1));
        rmax0 = fmaxf(rmax0, __shfl_xor_sync(0xffffffffu, rmax0, 2));
        rmax1 = fmaxf(rmax1, __shfl_xor_sync(0xffffffffu, rmax1, 1));
        rmax1 = fmaxf(rmax1, __shfl_xor_sync(0xffffffffu, rmax1, 2));
        float nm0 = fmaxf(m0, rmax0), nm1 = fmaxf(m1, rmax1);
        float c0 = __expf(m0 - nm0), c1 = __expf(m1 - nm1);
        m0 = nm0; m1 = nm1;

        float rs0 = 0.f, rs1 = 0.f;
#pragma unroll
        for (int n = 0; n < 8; n++) {
            sf[n][0] = __expf(sf[n][0] - m0);
            sf[n][1] = __expf(sf[n][1] - m0);
            sf[n][2] = __expf(sf[n][2] - m1);
            sf[n][3] = __expf(sf[n][3] - m1);
            rs0 += sf[n][0] + sf[n][1];
            rs1 += sf[n][2] + sf[n][3];
        }
        rs0 += __shfl_xor_sync(0xffffffffu, rs0, 1);
        rs0 += __shfl_xor_sync(0xffffffffu, rs0, 2);
        rs1 += __shfl_xor_sync(0xffffffffu, rs1, 1);
        rs1 += __shfl_xor_sync(0xffffffffu, rs1, 2);
        l0 = l0 * c0 + rs0;
        l1 = l1 * c1 + rs1;

#pragma unroll
        for (int n = 0; n < 16; n++) {
            of[n][0] *= c0; of[n][1] *= c0;
            of[n][2] *= c1; of[n][3] *= c1;
        }

        // ---- O += P @ V : 4 k16-steps (keys), 16 n-tiles (dh) ----
#pragma unroll
        for (int ks = 0; ks < 4; ks++) {
            unsigned a0 = pack_bf(sf[2*ks    ][0], sf[2*ks    ][1]);
            unsigned a1 = pack_bf(sf[2*ks    ][2], sf[2*ks    ][3]);
            unsigned a2 = pack_bf(sf[2*ks + 1][0], sf[2*ks + 1][1]);
            unsigned a3 = pack_bf(sf[2*ks + 1][2], sf[2*ks + 1][3]);
#pragma unroll
            for (int n = 0; n < 16; n++) {
                const unsigned* vb = uvc + (n * 8 + r) * LDVW + ks * 8 + c;
                mma_bf16(of[n][0], of[n][1], of[n][2], of[n][3],
                         a0, a1, a2, a3, vb[0], vb[4]);
            }
        }
        __syncthreads();   // done reading current buffers -> reusable next iter
    }

    // ---- normalize + write O ----
    const float i0 = 1.f / l0, i1 = 1.f / l1;
    float* O = g_att + (size_t)bh * kS * kDH + (size_t)q0g * kDH;
    const int row0 = qr + r, row1 = qr + r + 8;
#pragma unroll
    for (int n = 0; n < 16; n++) {
        int col = n * 8 + c * 2;
        *reinterpret_cast<float2*>(O + (size_t)row0 * kDH + col) =
            make_float2(of[n][0] * i0, of[n][1] * i0);
        *reinterpret_cast<float2*>(O + (size_t)row1 * kDH + col) =
            make_float2(of[n][2] * i1, of[n][3] * i1);
    }
}

// ---------------------------------------------------------------------------
// Kernel 3: out[b,s,:] = concat_h(O[b,h,s,:]) @ Wout + bout (unchanged)
// ---------------------------------------------------------------------------
__global__ __launch_bounds__(256) void out_kernel(
    const float* __restrict__ Wout, const float* __restrict__ bout,
    float* __restrict__ out)
{
    __shared__ float ws[64 * kDH];  // 32 KB
    __shared__ float xs[16 * 64];   // 4 KB

    const int t = threadIdx.x;
    const int row = t >> 4;
    const int dj  = t & 15;
    const int bs0 = blockIdx.x * 16;

    float acc[8];
#pragma unroll
    for (int j = 0; j < 8; j++) acc[j] = 0.f;

    for (int cch = 0; cch < 16; cch++) {
        const int i0 = cch * 64;
        __syncthreads();
        {
            const float4* Wsrc = reinterpret_cast<const float4*>(Wout + (size_t)i0 * kDH);
#pragma unroll
            for (int j = 0; j < 8; j++)
                reinterpret_cast<float4*>(ws)[t + j * 256] = Wsrc[t + j * 256];
        }
#pragma unroll
        for (int j = 0; j < 4; j++) {
            int i  = t + j * 256;
            int rr = i >> 6, ii = i & 63;
            int gi = i0 + ii;
            int hh = gi >> 7, e = gi & 127;
            int bs = bs0 + rr;
            int b  = bs / kS, s = bs % kS;
            xs[rr * 64 + ii] = g_att[(((size_t)b * kH + hh) * kS + s) * kDH + e];
        }
        __syncthreads();

#pragma unroll 8
        for (int ii = 0; ii < 64; ii++) {
            float xv = xs[row * 64 + ii];
#pragma unroll
            for (int j = 0; j < 8; j++)
                acc[j] = fmaf(xv, ws[ii * kDH + dj + 16 * j], acc[j]);
        }
    }

    const int bs = bs0 + row;
#pragma unroll
    for (int j = 0; j < 8; j++) {
        int d = dj + 16 * j;
        out[(size_t)bs * kDH + d] = acc[j] + bout[d];
    }
}

// ---------------------------------------------------------------------------
extern "C" void kernel_launch(void* const* d_in, const int* in_sizes, int n_in,
                              void* d_out, int out_size)
{
    (void)in_sizes; (void)n_in; (void)out_size;
    const float* f0   = (const float*)d_in[0];
    const float* u0   = (const float*)d_in[1];
    const float* f1   = (const float*)d_in[2];
    const float* u1   = (const float*)d_in[3];
    const float* Wf   = (const float*)d_in[4];
    const float* bf   = (const float*)d_in[5];
    const float* Wu   = (const float*)d_in[6];
    const float* bu   = (const float*)d_in[7];
    const float* Wout = (const float*)d_in[8];
    const float* bout = (const float*)d_in[9];
    float* out = (float*)d_out;

    // idempotent host-side attribute set; safe under graph capture
    cudaFuncSetAttribute(attn_kernel,
                         cudaFuncAttributeMaxDynamicSharedMemorySize, ATTN_SMEM_BYTES);

    proj_kernel<<<dim3(68, 3, kB * kH), 256>>>(f0, u0, f1, u1, Wf, bf, Wu, bu);
    attn_kernel<<<dim3(kS / QTT, kB * kH), 256, ATTN_SMEM_BYTES>>>();
    out_kernel<<<(kB * kS) / 16, 256>>>(Wout, bout, out);
}